// round 1
// baseline (speedup 1.0000x reference)
#include <cuda_runtime.h>

// Scratch for projected NDC xy per vertex per batch. Static __device__ array
// (allocation-free per harness rules). 64K float2 = 512 KB, far above B*V=7778.
#define MAX_BV 65536
__device__ float2 g_proj[MAX_BV];

__global__ void zero_out_kernel(float* __restrict__ out, int n) {
    int i = blockIdx.x * blockDim.x + threadIdx.x;
    if (i < n) out[i] = 0.0f;
}

// Project vertices exactly like the reference:
//   f  = cams[b,0]; cx = cams[b,1]; cy = cams[b,2]
//   image_size = cams[0,1] * 2
//   px = f*x/z + cx; ndc = px/image_size*2 - 1   (z = v.z, norm_z = 0)
__global__ void project_kernel(const float* __restrict__ verts,
                               const float* __restrict__ cams,
                               int B, int V) {
    int i = blockIdx.x * blockDim.x + threadIdx.x;
    if (i >= B * V) return;
    int b = i / V;
    float f  = cams[b * 3 + 0];
    float cx = cams[b * 3 + 1];
    float cy = cams[b * 3 + 2];
    float image_size = cams[1] * 2.0f;   // cams[0,1]*2 per reference
    float x = verts[i * 3 + 0];
    float y = verts[i * 3 + 1];
    float z = verts[i * 3 + 2];
    float px = f * x / z + cx;
    float py = f * y / z + cy;
    float nx = px / image_size * 2.0f - 1.0f;
    float ny = py / image_size * 2.0f - 1.0f;
    g_proj[i] = make_float2(nx, ny);
}

// One CTA per (batch, face). 32x4 threads stride the triangle's pixel bbox.
// Edge functions evaluated in NDC space with the reference's formula.
__global__ void __launch_bounds__(128)
raster_kernel(const int* __restrict__ faces,
              float* __restrict__ out,
              int B, int V, int F, int S) {
    int t = blockIdx.x;            // 0 .. B*F-1
    int b = t / F;

    const int* fv = faces + t * 3;
    float2 v0 = g_proj[b * V + fv[0]];
    float2 v1 = g_proj[b * V + fv[1]];
    float2 v2 = g_proj[b * V + fv[2]];

    // Area & validity cull (matches reference: |area| > 1e-12 in NDC units)
    float area = (v1.x - v0.x) * (v2.y - v0.y) - (v1.y - v0.y) * (v2.x - v0.x);
    if (!(fabsf(area) > 1e-12f)) return;

    float minx = fminf(v0.x, fminf(v1.x, v2.x));
    float maxx = fmaxf(v0.x, fmaxf(v1.x, v2.x));
    float miny = fminf(v0.y, fminf(v1.y, v2.y));
    float maxy = fmaxf(v0.y, fmaxf(v1.y, v2.y));

    // Pixel-center ndc: p_i = (2i+1)/S - 1  ->  i = (p+1)*S/2 - 0.5
    // +-1 pixel margin makes rounding at the bbox edge harmless.
    float half = 0.5f * (float)S;
    int x0 = max(0,     (int)floorf((minx + 1.0f) * half - 0.5f) - 1);
    int x1 = min(S - 1, (int)ceilf ((maxx + 1.0f) * half - 0.5f) + 1);
    int y0 = max(0,     (int)floorf((miny + 1.0f) * half - 0.5f) - 1);
    int y1 = min(S - 1, (int)ceilf ((maxy + 1.0f) * half - 0.5f) + 1);
    if (x1 < x0 || y1 < y0) return;

    float invS = 1.0f / (float)S;
    float* outb = out + b * S * S;

    int tx = threadIdx.x;          // 0..31, strides x (coalesced stores)
    int ty = threadIdx.y;          // 0..3,  strides y

    float e0x = v2.y - v1.y, e0y = v2.x - v1.x;   // edge v1->v2
    float e1x = v0.y - v2.y, e1y = v0.x - v2.x;   // edge v2->v0
    float e2x = v1.y - v0.y, e2y = v1.x - v0.x;   // edge v0->v1

    for (int iy = y0 + ty; iy <= y1; iy += 4) {
        float py = (2.0f * (float)iy + 1.0f) * invS - 1.0f;
        float r0 = (py - v1.y) * e0y;
        float r1 = (py - v2.y) * e1y;
        float r2 = (py - v0.y) * e2y;
        float* row = outb + iy * S;
        for (int ix = x0 + tx; ix <= x1; ix += 32) {
            float px = (2.0f * (float)ix + 1.0f) * invS - 1.0f;
            float w0 = (px - v1.x) * e0x - r0;
            float w1 = (px - v2.x) * e1x - r1;
            float w2 = (px - v0.x) * e2x - r2;
            bool pos = (w0 >= 0.0f) & (w1 >= 0.0f) & (w2 >= 0.0f);
            bool neg = (w0 <= 0.0f) & (w1 <= 0.0f) & (w2 <= 0.0f);
            if (pos | neg) row[ix] = 1.0f;
        }
    }
}

extern "C" void kernel_launch(void* const* d_in, const int* in_sizes, int n_in,
                              void* d_out, int out_size) {
    const float* verts = (const float*)d_in[0];   // [B,V,3] fp32
    const int*   faces = (const int*)d_in[1];     // [B,F,3] int32
    const float* cams  = (const float*)d_in[2];   // [B,3]   fp32

    int B = in_sizes[2] / 3;
    int V = in_sizes[0] / (3 * B);
    int F = in_sizes[1] / (3 * B);
    int S = 256;                                   // out_size = B*S*S
    // derive S from out_size to be robust: S*S = out_size/B
    {
        int ss = out_size / B;
        int s = 1;
        while (s * s < ss) s <<= 1;
        if (s * s == ss) S = s;
    }

    float* out = (float*)d_out;

    zero_out_kernel<<<(out_size + 255) / 256, 256>>>(out, out_size);
    project_kernel<<<(B * V + 127) / 128, 128>>>(verts, cams, B, V);

    dim3 blk(32, 4);
    raster_kernel<<<B * F, blk>>>(faces, out, B, V, F, S);
}